// round 3
// baseline (speedup 1.0000x reference)
#include <cuda_runtime.h>

// FlowNetC correlation on GB300 — round 3: packed f32x2 FMA (FFMA2).
// out[b, dy*21+dx, y, x] = (1/256) * sum_c in1[b,c,y,x] * in2[b,c, y+2dy-20, x+2dx-20]
//
// Block = (dy-group of 7, y, b). 7 warps, one warp per dy, 1 block/SM (no reg cap:
// R2 showed forcing 128 regs spills the 84-acc working set into the inner loop).
// Accumulators packed 2-wide: acc01[j] = (acc_x0[j], acc_x1[j]) updated by one
// fma.rn.f32x2 with multiplier pair (a0,a1) and r-pair (r[j], r[j+1]).
// Even-aligned r pairs are free (LDS.128 register quads); odd-aligned pairs are
// built with mov.b64 (22 MOVs/channel on the alu pipe, under the fma budget).

#define NW        7
#define CK        8
#define NTHREADS  (NW * 32)  // 224
#define C_TOT     256
#define NCHUNK    (C_TOT / CK)   // 32
#define H         96
#define W         128
#define DD        21

struct __align__(16) Smem {
    float in2s[NW][CK][2][84];   // [dy][c][parity][pad10 | 64 | pad10] 37632 B
    float in1s[CK][2][64];       //                                      4096 B
    float stage[NW][128];        // output transpose staging             3584 B
};                               // 45312 B (static, 1 block/SM)

__device__ __forceinline__ unsigned long long pk(float lo, float hi) {
    unsigned long long r;
    asm("mov.b64 %0, {%1, %2};" : "=l"(r) : "f"(lo), "f"(hi));
    return r;
}
__device__ __forceinline__ void fma2(unsigned long long& acc,
                                     unsigned long long a,
                                     unsigned long long b) {
    asm("fma.rn.f32x2 %0, %1, %2, %0;" : "+l"(acc) : "l"(a), "l"(b));
}
__device__ __forceinline__ float f2lo(unsigned long long v) {
    return __uint_as_float((unsigned)(v & 0xffffffffull));
}
__device__ __forceinline__ float f2hi(unsigned long long v) {
    return __uint_as_float((unsigned)(v >> 32));
}

__global__ void __launch_bounds__(NTHREADS) corr_kernel(
    const float* __restrict__ g_in1,
    const float* __restrict__ g_in2,
    float*       __restrict__ g_out)
{
    __shared__ Smem sm;

    const int b    = blockIdx.z;
    const int y    = blockIdx.y;
    const int dyg  = blockIdx.x;          // 0..2
    const int tid  = threadIdx.x;
    const int w    = tid >> 5;            // warp = local dy
    const int lane = tid & 31;
    const int p    = lane >> 4;           // parity
    const int g    = lane & 15;
    const int U    = g << 2;              // base deint index (multiple of 4)
    const int dy0  = dyg * NW;

    // Zero x-pad regions (u in [0,10) and [74,84)) once.
    for (int e = tid; e < NW * CK * 2 * 20; e += NTHREADS) {
        int u = e % 20; u = (u < 10) ? u : (u + 64);
        int rest = e / 20;
        int pp = rest & 1;
        int cc = (rest >> 1) & (CK - 1);
        int ww = rest >> 4;
        sm.in2s[ww][cc][pp][u] = 0.0f;
    }

    const size_t plane = (size_t)H * W;
    const size_t cstep = (size_t)CK * plane;

    unsigned long long acc01[21], acc23[21];
    #pragma unroll
    for (int j = 0; j < 21; ++j) { acc01[j] = 0ull; acc23[j] = 0ull; }

    // ---- loop-invariant loader state (in2: 1792 float4/chunk, 8 per thread) ----
    const float* gp2[8];
    float*       sp2[8];
    bool         l_ok[8];
    #pragma unroll
    for (int q = 0; q < 8; ++q) {
        int e4   = q * NTHREADS + tid;
        int col4 = e4 & 31;
        int cc   = (e4 >> 5) & 7;
        int ww   = e4 >> 8;                 // 0..6
        int row2 = y + 2 * (dy0 + ww) - 20; // [-20, 115]
        l_ok[q]  = (row2 >= 0) && (row2 < H);
        gp2[q]   = g_in2 + ((size_t)b * C_TOT + cc) * plane + row2 * W + col4 * 4;
        sp2[q]   = &sm.in2s[ww][cc][0][2 * col4 + 10];   // odd parity = +84
    }
    // in1: 256 float4/chunk: slot A for all threads, slot B for tid<32 (cc=7)
    const float* gp1a = g_in1 + ((size_t)b * C_TOT + (tid >> 5)) * plane
                              + (size_t)y * W + (tid & 31) * 4;
    const float* gp1b = g_in1 + ((size_t)b * C_TOT + 7) * plane
                              + (size_t)y * W + tid * 4;
    float* sp1a = &sm.in1s[tid >> 5][0][2 * (tid & 31)];   // odd = +64
    float* sp1b = &sm.in1s[7][0][2 * tid];

    float4 pf2[8], pf1a, pf1b;

    // prefetch chunk 0
    #pragma unroll
    for (int q = 0; q < 8; ++q)
        pf2[q] = l_ok[q] ? *(const float4*)gp2[q] : make_float4(0.f, 0.f, 0.f, 0.f);
    pf1a = *(const float4*)gp1a;
    if (tid < 32) pf1b = *(const float4*)gp1b;

    for (int k = 0; k < NCHUNK; ++k) {
        __syncthreads();  // previous chunk fully consumed

        // store prefetched chunk, de-interleaving by parity
        #pragma unroll
        for (int q = 0; q < 8; ++q) {
            *(float2*)(sp2[q])      = make_float2(pf2[q].x, pf2[q].z);
            *(float2*)(sp2[q] + 84) = make_float2(pf2[q].y, pf2[q].w);
        }
        *(float2*)(sp1a)      = make_float2(pf1a.x, pf1a.z);
        *(float2*)(sp1a + 64) = make_float2(pf1a.y, pf1a.w);
        if (tid < 32) {
            *(float2*)(sp1b)      = make_float2(pf1b.x, pf1b.z);
            *(float2*)(sp1b + 64) = make_float2(pf1b.y, pf1b.w);
        }
        __syncthreads();  // smem ready

        // prefetch chunk k+1
        if (k + 1 < NCHUNK) {
            #pragma unroll
            for (int q = 0; q < 8; ++q) {
                gp2[q] += cstep;
                pf2[q] = l_ok[q] ? *(const float4*)gp2[q]
                                 : make_float4(0.f, 0.f, 0.f, 0.f);
            }
            gp1a += cstep;
            pf1a = *(const float4*)gp1a;
            if (tid < 32) { gp1b += cstep; pf1b = *(const float4*)gp1b; }
        }

        // ---- compute chunk k: per channel 7x LDS.128 -> 42 FFMA2 ----
        #pragma unroll
        for (int cc = 0; cc < CK; ++cc) {
            float4 av = *(const float4*)&sm.in1s[cc][p][U];
            unsigned long long a01 = pk(av.x, av.y);
            unsigned long long a23 = pk(av.z, av.w);
            float r[24];
            #pragma unroll
            for (int q = 0; q < 6; ++q)
                *(float4*)&r[4 * q] = *(const float4*)&sm.in2s[w][cc][p][U + 4 * q];
            // odd-aligned pairs o[k] = (r[2k+1], r[2k+2])
            unsigned long long o[11];
            #pragma unroll
            for (int kk = 0; kk < 11; ++kk) o[kk] = pk(r[2 * kk + 1], r[2 * kk + 2]);
            #pragma unroll
            for (int j = 0; j < 21; ++j) {
                // acc01[j]: lanes (x=U+0 uses r[j], x=U+1 uses r[j+1])
                // acc23[j]: lanes (x=U+2 uses r[j+2], x=U+3 uses r[j+3])
                unsigned long long rp0 = (j & 1) ? o[(j - 1) >> 1]
                                                 : pk(r[j], r[j + 1]);
                unsigned long long rp1 = (j & 1) ? o[(j + 1) >> 1]
                                                 : pk(r[j + 2], r[j + 3]);
                fma2(acc01[j], a01, rp0);
                fma2(acc23[j], a23, rp1);
            }
        }
    }

    // ---- epilogue: smem transpose -> fully coalesced 512B row stores ----
    const float scale = 1.0f / 256.0f;
    const int   dy    = dy0 + w;
    float* outb = g_out + (((size_t)b * (DD * DD)) * H + y) * W;
    #pragma unroll
    for (int j = 0; j < 21; ++j) {
        sm.stage[w][2 * (U + 0) + p] = f2lo(acc01[j]) * scale;
        sm.stage[w][2 * (U + 1) + p] = f2hi(acc01[j]) * scale;
        sm.stage[w][2 * (U + 2) + p] = f2lo(acc23[j]) * scale;
        sm.stage[w][2 * (U + 3) + p] = f2hi(acc23[j]) * scale;
        __syncwarp();
        float4 v = *(const float4*)&sm.stage[w][lane * 4];
        *(float4*)(outb + (size_t)(dy * DD + j) * plane + lane * 4) = v;
        __syncwarp();
    }
}

extern "C" void kernel_launch(void* const* d_in, const int* in_sizes, int n_in,
                              void* d_out, int out_size)
{
    (void)in_sizes; (void)n_in; (void)out_size;
    const float* in1 = (const float*)d_in[0];
    const float* in2 = (const float*)d_in[1];
    float*       out = (float*)d_out;

    dim3 grid(3, H, 8);      // (dy-group, y, b)
    dim3 block(NTHREADS);    // 224 = 7 warps
    corr_kernel<<<grid, block>>>(in1, in2, out);
}

// round 4
// speedup vs baseline: 1.4197x; 1.4197x over previous
#include <cuda_runtime.h>

// FlowNetC correlation on GB300 — round 4: banded tf32 tensor-core (m16n8k8 HMMA).
//
// out[b, dy*21+dx, y, x] = (1/256) * sum_c in1[b,c,y,x] * in2[b,c, y+2dy-20, x+2dx-20]
//
// Parity de-interleave: x = 2*xh+p, and out[xh,dx] = sum_c A[c,xh] * B[c,xh+dx]
// where B[c,u] = in2p at x' = 2(u-10)+p  (xp = x'+20 = 2u+p in padded coords).
// Banded A^T*B: per m16 tile (16 xh) only 5 n8 tiles are needed (u in [xh0,xh0+40)).
//
// Block = (dyg of 7 dy, y, b). 14 warps: warp w -> (dyl = w>>1, parity = w&1).
// Per warp: 4 m-tiles x 5 n-tiles x 32 k8-steps of mma.m16n8k8.tf32, 80 acc regs.
// Smem: physical interleaved tiles, double-buffered cp.async; de-interleave via
// stride-2 fragment addressing. Pads + OOB-dy rows pre-zeroed once.

#define DD      21
#define HH      96
#define WW      128
#define C_TOT   256
#define CKT     8                // channels per stage (= one k8 step)
#define NCH     (C_TOT / CKT)    // 32 chunks
#define NTH     448              // 14 warps
#define SBROW   176              // padded B row (xp: 0..167 used)
#define SAROW   132              // padded A row (x: 0..127 used)
#define B_WST   (CKT * 7 * SBROW)   // 9856 words / stage
#define A_WST   (CKT * SAROW)       // 1056 words / stage
#define A_BASE  (2 * B_WST)         // 19712
#define SMEM_WORDS (2 * B_WST + 2 * A_WST)  // 21824 words = 87296 B

__device__ __forceinline__ void cp16(unsigned dst, const float* src) {
    asm volatile("cp.async.cg.shared.global [%0], [%1], 16;"
                 :: "r"(dst), "l"(src));
}
__device__ __forceinline__ unsigned ld_tf32(const float* p) {
    unsigned r; float v = *p;
    asm("cvt.rna.tf32.f32 %0, %1;" : "=r"(r) : "f"(v));
    return r;
}
__device__ __forceinline__ void mma_tf32(float (&d)[4],
                                         unsigned a0, unsigned a1,
                                         unsigned a2, unsigned a3,
                                         unsigned b0, unsigned b1) {
    asm volatile(
        "mma.sync.aligned.m16n8k8.row.col.f32.tf32.tf32.f32 "
        "{%0,%1,%2,%3}, {%4,%5,%6,%7}, {%8,%9}, {%0,%1,%2,%3};"
        : "+f"(d[0]), "+f"(d[1]), "+f"(d[2]), "+f"(d[3])
        : "r"(a0), "r"(a1), "r"(a2), "r"(a3), "r"(b0), "r"(b1));
}

extern __shared__ float smem[];

__global__ void __launch_bounds__(NTH, 1) corr_mma(
    const float* __restrict__ g_in1,
    const float* __restrict__ g_in2,
    float*       __restrict__ g_out)
{
    const int b    = blockIdx.z;
    const int y    = blockIdx.y;
    const int dyg  = blockIdx.x;      // 0..2
    const int dy0  = dyg * 7;
    const int tid  = threadIdx.x;
    const int w    = tid >> 5;
    const int lane = tid & 31;
    const int dyl  = w >> 1;          // 0..6
    const int par  = w & 1;
    const int g    = lane >> 2;       // 0..7
    const int t    = lane & 3;        // 0..3

    const size_t plane = (size_t)HH * WW;

    // Zero all smem once: pads + OOB-dy rows stay zero; interiors get
    // overwritten every chunk by cp.async.
    for (int i = tid; i < SMEM_WORDS; i += NTH) smem[i] = 0.0f;

    // ---- cp.async slot setup: 2048 16B-chunks per stage, 5 slots/thread ----
    const unsigned sm0 = (unsigned)__cvta_generic_to_shared(smem);
    const float* srcs[5];
    unsigned     dsts[5];   // stage-0 smem byte address
    unsigned     sstr[5];   // byte stride to stage 1
    bool         val[5];
    #pragma unroll
    for (int q = 0; q < 5; ++q) {
        int idx = q * NTH + tid;
        if (idx < 1792) {                       // B: in2 rows
            int rowid = idx >> 5, ch = idx & 31;
            int c  = rowid / 7, dl = rowid % 7;
            int row2 = y + 2 * (dy0 + dl) - 20;
            val[q]  = (row2 >= 0) && (row2 < HH);
            srcs[q] = g_in2 + ((size_t)b * C_TOT + c) * plane
                            + (size_t)(val[q] ? row2 : 0) * WW + ch * 4;
            dsts[q] = sm0 + (unsigned)(c * (7 * SBROW) + dl * SBROW + 20 + ch * 4) * 4u;
            sstr[q] = B_WST * 4u;
        } else if (idx < 2048) {                // A: in1 row
            int a2 = idx - 1792;
            int c  = a2 >> 5, ch = a2 & 31;
            val[q]  = true;
            srcs[q] = g_in1 + ((size_t)b * C_TOT + c) * plane
                            + (size_t)y * WW + ch * 4;
            dsts[q] = sm0 + (unsigned)(A_BASE + c * SAROW + ch * 4) * 4u;
            sstr[q] = A_WST * 4u;
        } else {
            val[q] = false; srcs[q] = g_in1; dsts[q] = sm0; sstr[q] = 0;
        }
    }

    __syncthreads();   // zeroing complete before first cp.async writes

    float acc[20][4];
    #pragma unroll
    for (int f = 0; f < 20; ++f)
        #pragma unroll
        for (int e = 0; e < 4; ++e) acc[f][e] = 0.0f;

    // ---- prologue: issue chunk 0 ----
    #pragma unroll
    for (int q = 0; q < 5; ++q) {
        if (val[q]) cp16(dsts[q], srcs[q]);
        srcs[q] += (size_t)CKT * plane;
    }
    asm volatile("cp.async.commit_group;");

    for (int k = 0; k < NCH; ++k) {
        if (k + 1 < NCH) {
            const unsigned so = ((k + 1) & 1);
            #pragma unroll
            for (int q = 0; q < 5; ++q) {
                if (val[q]) cp16(dsts[q] + so * sstr[q], srcs[q]);
                srcs[q] += (size_t)CKT * plane;
            }
            asm volatile("cp.async.commit_group;");
            asm volatile("cp.async.wait_group 1;");
        } else {
            asm volatile("cp.async.wait_group 0;");
        }
        __syncthreads();   // chunk k visible to all warps

        const float* As = smem + A_BASE + (k & 1) * A_WST;
        const float* Bs = smem + (k & 1) * B_WST + dyl * SBROW;

        // A fragments (m16k8, row-major): row = xh, col = c
        unsigned a[4][4];
        #pragma unroll
        for (int mt = 0; mt < 4; ++mt) {
            int x0 = 2 * (16 * mt + g) + par;
            a[mt][0] = ld_tf32(As + t * SAROW + x0);
            a[mt][1] = ld_tf32(As + t * SAROW + x0 + 16);
            a[mt][2] = ld_tf32(As + (t + 4) * SAROW + x0);
            a[mt][3] = ld_tf32(As + (t + 4) * SAROW + x0 + 16);
        }
        // B fragments (k8n8, col-major): col = u (deint), row = c
        #pragma unroll
        for (int j = 0; j < 11; ++j) {
            int xc = 2 * (8 * j + g) + par;
            unsigned b0 = ld_tf32(Bs + t * (7 * SBROW) + xc);
            unsigned b1 = ld_tf32(Bs + (t + 4) * (7 * SBROW) + xc);
            #pragma unroll
            for (int mt = 0; mt < 4; ++mt)
                if (2 * mt <= j && j <= 2 * mt + 4)
                    mma_tf32(acc[mt * 5 + (j - 2 * mt)],
                             a[mt][0], a[mt][1], a[mt][2], a[mt][3], b0, b1);
        }
        __syncthreads();   // all warps done with buffer (k&1) before overwrite
    }

    // ---- epilogue: band-extract + scatter stores ----
    const float scale = 1.0f / 256.0f;
    const int   dy    = dy0 + dyl;
    float* ob = g_out + ((size_t)(b * (DD * DD) + dy * DD)) * plane
                      + (size_t)y * WW + par;
    #pragma unroll
    for (int mt = 0; mt < 4; ++mt) {
        #pragma unroll
        for (int i = 0; i < 5; ++i) {
            const int u0 = 8 * (2 * mt + i);
            const float* f = acc[mt * 5 + i];
            #pragma unroll
            for (int e = 0; e < 4; ++e) {
                int r   = (e >= 2) ? (g + 8) : g;
                int col = 2 * t + (e & 1);
                int xh  = 16 * mt + r;
                int dx  = u0 + col - xh;
                if (dx >= 0 && dx < DD)
                    ob[(size_t)dx * plane + 2 * xh] = f[e] * scale;
            }
        }
    }
}

extern "C" void kernel_launch(void* const* d_in, const int* in_sizes, int n_in,
                              void* d_out, int out_size)
{
    (void)in_sizes; (void)n_in; (void)out_size;
    const float* in1 = (const float*)d_in[0];
    const float* in2 = (const float*)d_in[1];
    float*       out = (float*)d_out;

    cudaFuncSetAttribute(corr_mma, cudaFuncAttributeMaxDynamicSharedMemorySize,
                         SMEM_WORDS * 4);

    dim3 grid(3, HH, 8);     // (dy-group, y, b) -> 2304 blocks
    dim3 block(NTH);         // 448 = 14 warps
    corr_mma<<<grid, block, SMEM_WORDS * 4>>>(in1, in2, out);
}